// round 15
// baseline (speedup 1.0000x reference)
#include <cuda_runtime.h>
#include <cuda_fp16.h>
#include <cstdint>

// Problem constants (fixed shapes)
#define K_DIM 4096
#define N_DIM 11008
#define M_DIM 8192
#define NPACK 1376   /* N/8 packed int32 columns */

// GEMM tiling: CTA 128x128x64, 16 warps (4x4), warp tile 32x32, 512 threads,
// 2 CTAs/SM (32 warps/SM), 3-stage cp.async, fp32-accum mma.
#define BM 128
#define BN 128
#define BK 64
#define NT 512
#define NSTAGE 3
#define SA_STRIDE 72    /* halves per A row (144B), conflict-free ldmatrix */
#define SB_STRIDE 136   /* halves per B row (272B), conflict-free ldmatrix */
#define SA_STAGE_HALVES (BM * SA_STRIDE)   /* 9216  -> 18432 B */
#define SB_STAGE_HALVES (BK * SB_STRIDE)   /* 8704  -> 17408 B */
#define KT_ITERS (K_DIM / BK)              /* 64 */

// Scratch (static __device__ arrays: allowed)
__device__ __half g_W[(size_t)K_DIM * N_DIM];   // 90 MB dequantized weights (fp16, [K,N])
__device__ __half g_X[(size_t)M_DIM * K_DIM];   // 64 MB activations fp32->fp16

#define CP_ASYNC_CG(dst, src) \
    asm volatile("cp.async.cg.shared.global [%0], [%1], 16;\n" :: "r"(dst), "l"(src))
#define CP_COMMIT() asm volatile("cp.async.commit_group;\n" ::)
#define CP_WAIT(n)  asm volatile("cp.async.wait_group %0;\n" :: "n"(n))

// ---------------------------------------------------------------------------
// Kernel 0: convert x (fp32 from harness) -> fp16 g_X. 8 elements/thread.
// ---------------------------------------------------------------------------
__global__ void convert_x_kernel(const float* __restrict__ x)
{
    size_t i = ((size_t)blockIdx.x * blockDim.x + threadIdx.x) * 8;
    if (i >= (size_t)M_DIM * K_DIM) return;
    float4 f0 = *reinterpret_cast<const float4*>(x + i);
    float4 f1 = *reinterpret_cast<const float4*>(x + i + 4);
    __half h[8];
    h[0] = __float2half(f0.x); h[1] = __float2half(f0.y);
    h[2] = __float2half(f0.z); h[3] = __float2half(f0.w);
    h[4] = __float2half(f1.x); h[5] = __float2half(f1.y);
    h[6] = __float2half(f1.z); h[7] = __float2half(f1.w);
    *reinterpret_cast<uint4*>(&g_X[i]) = *reinterpret_cast<uint4*>(h);
}

// ---------------------------------------------------------------------------
// Kernel 1: AWQ 4-bit dequant -> fp16 g_W[k][n] (nibble order {0,4,1,5,2,6,3,7})
// ---------------------------------------------------------------------------
__global__ void dequant_kernel(const int* __restrict__ qw,
                               const int* __restrict__ qz,
                               const float* __restrict__ sc)
{
    int idx = blockIdx.x * blockDim.x + threadIdx.x;
    if (idx >= K_DIM * NPACK) return;
    int k = idx / NPACK;
    int p = idx - k * NPACK;

    int w = qw[idx];
    int z = qz[(k >> 7) * NPACK + p];

    const float* sp = sc + (size_t)(k >> 7) * N_DIM + p * 8;
    float4 s0 = *reinterpret_cast<const float4*>(sp);
    float4 s1 = *reinterpret_cast<const float4*>(sp + 4);
    float sf[8] = {s0.x, s0.y, s0.z, s0.w, s1.x, s1.y, s1.z, s1.w};

    const int shift[8] = {0, 16, 4, 20, 8, 24, 12, 28};
    __half outv[8];
#pragma unroll
    for (int j = 0; j < 8; j++) {
        int iw = (w >> shift[j]) & 15;
        int iz = (z >> shift[j]) & 15;
        outv[j] = __float2half((float)(iw - iz) * sf[j]);
    }
    *reinterpret_cast<uint4*>(&g_W[(size_t)k * N_DIM + p * 8]) =
        *reinterpret_cast<uint4*>(outv);
}

// ---------------------------------------------------------------------------
// Kernel 2: fp16 mma.sync GEMM, fp32 accum, fused bias, fp32 output.
// 128x128x64 CTA tile, 512 threads, 16 warps (4x4) warp tile 32x32,
// 2 CTAs/SM => 32 warps/SM (occupancy 50%), 3-stage cp.async,
// one __syncthreads per K-chunk.
// ---------------------------------------------------------------------------
__global__ void __launch_bounds__(NT, 2)
gemm_kernel(const float* __restrict__ bias, float* __restrict__ out)
{
    extern __shared__ __half dsm[];
    __half* sA = dsm;                                    // [NSTAGE][BM][SA_STRIDE]
    __half* sB = dsm + NSTAGE * SA_STAGE_HALVES;         // [NSTAGE][BK][SB_STRIDE]

    const int tid  = threadIdx.x;
    const int wid  = tid >> 5;
    const int lane = tid & 31;
    const int bm0  = blockIdx.x * BM;
    const int bn0  = blockIdx.y * BN;

    const int wm = (wid >> 2) * 32;   // warp row offset (4 groups of 32)
    const int wn = (wid & 3) * 32;    // warp col offset (4 groups of 32)

    float acc[2][4][4];
#pragma unroll
    for (int i = 0; i < 2; i++)
#pragma unroll
        for (int j = 0; j < 4; j++)
#pragma unroll
            for (int r = 0; r < 4; r++) acc[i][j][r] = 0.f;

    const __half* gA = g_X + (size_t)bm0 * K_DIM;
    const __half* gB = g_W + bn0;

    // Loader: A = 1024 16B-chunks (row=c>>3, k8=c&7); B = 1024 (row=d>>4, n8=d&15)
#define ISSUE_STAGE(buf, kt_)                                                        \
    do {                                                                             \
        const int kk = (kt_) * BK;                                                   \
        __half* aS = sA + (buf) * SA_STAGE_HALVES;                                   \
        __half* bS = sB + (buf) * SB_STAGE_HALVES;                                   \
        _Pragma("unroll")                                                            \
        for (int i = 0; i < 2; i++) {                                                \
            int c = tid + i * NT;                                                    \
            int row = c >> 3, k8 = c & 7;                                            \
            uint32_t dst = (uint32_t)__cvta_generic_to_shared(                       \
                aS + row * SA_STRIDE + k8 * 8);                                      \
            CP_ASYNC_CG(dst, gA + (size_t)row * K_DIM + kk + k8 * 8);                \
        }                                                                            \
        _Pragma("unroll")                                                            \
        for (int i = 0; i < 2; i++) {                                                \
            int d = tid + i * NT;                                                    \
            int row = d >> 4, n8 = d & 15;                                           \
            uint32_t dst = (uint32_t)__cvta_generic_to_shared(                       \
                bS + row * SB_STRIDE + n8 * 8);                                      \
            CP_ASYNC_CG(dst, gB + (size_t)(kk + row) * N_DIM + n8 * 8);              \
        }                                                                            \
        CP_COMMIT();                                                                 \
    } while (0)

    // Prologue: prefetch stages 0,1
    ISSUE_STAGE(0, 0);
    ISSUE_STAGE(1, 1);

    for (int kt = 0; kt < KT_ITERS; kt++) {
        const int s = kt % 3;
        if (kt + 2 < KT_ITERS) CP_WAIT(1);
        else                   CP_WAIT(0);
        __syncthreads();   // stage kt visible; all warps done with buffer being refilled
        if (kt + 2 < KT_ITERS) ISSUE_STAGE((kt + 2) % 3, kt + 2);

        const __half* aS = sA + s * SA_STAGE_HALVES;
        const __half* bS = sB + s * SB_STAGE_HALVES;

#pragma unroll
        for (int ks = 0; ks < 4; ks++) {
            const int k16 = ks * 16;
            uint32_t a[2][4];
#pragma unroll
            for (int mi = 0; mi < 2; mi++) {
                uint32_t addr = (uint32_t)__cvta_generic_to_shared(
                    aS + (wm + mi * 16 + (lane & 15)) * SA_STRIDE + k16 + 8 * (lane >> 4));
                asm volatile(
                    "ldmatrix.sync.aligned.m8n8.x4.shared.b16 {%0,%1,%2,%3}, [%4];"
                    : "=r"(a[mi][0]), "=r"(a[mi][1]), "=r"(a[mi][2]), "=r"(a[mi][3])
                    : "r"(addr));
            }
            uint32_t b[4][2];
#pragma unroll
            for (int nj = 0; nj < 2; nj++) {
                uint32_t t0, t1, t2, t3;
                uint32_t addr = (uint32_t)__cvta_generic_to_shared(
                    bS + (k16 + (lane & 15)) * SB_STRIDE + wn + nj * 16 + 8 * (lane >> 4));
                asm volatile(
                    "ldmatrix.sync.aligned.m8n8.x4.trans.shared.b16 {%0,%1,%2,%3}, [%4];"
                    : "=r"(t0), "=r"(t1), "=r"(t2), "=r"(t3)
                    : "r"(addr));
                b[nj * 2 + 0][0] = t0; b[nj * 2 + 0][1] = t1;
                b[nj * 2 + 1][0] = t2; b[nj * 2 + 1][1] = t3;
            }
#pragma unroll
            for (int mi = 0; mi < 2; mi++)
#pragma unroll
                for (int ni = 0; ni < 4; ni++) {
                    asm volatile(
                        "mma.sync.aligned.m16n8k16.row.col.f32.f16.f16.f32 "
                        "{%0,%1,%2,%3}, {%4,%5,%6,%7}, {%8,%9}, {%0,%1,%2,%3};"
                        : "+f"(acc[mi][ni][0]), "+f"(acc[mi][ni][1]),
                          "+f"(acc[mi][ni][2]), "+f"(acc[mi][ni][3])
                        : "r"(a[mi][0]), "r"(a[mi][1]), "r"(a[mi][2]), "r"(a[mi][3]),
                          "r"(b[ni][0]), "r"(b[ni][1]));
                }
        }
    }

    // Epilogue: fp32 acc + fp32 bias -> fp16 round -> fp32 output, float2 stores
#pragma unroll
    for (int mi = 0; mi < 2; mi++) {
        int row0 = bm0 + wm + mi * 16 + (lane >> 2);
#pragma unroll
        for (int ni = 0; ni < 4; ni++) {
            int col = bn0 + wn + ni * 8 + (lane & 3) * 2;
            float2 bb = *reinterpret_cast<const float2*>(bias + col);
            float r00 = __half2float(__float2half(acc[mi][ni][0] + bb.x));
            float r01 = __half2float(__float2half(acc[mi][ni][1] + bb.y));
            float r10 = __half2float(__float2half(acc[mi][ni][2] + bb.x));
            float r11 = __half2float(__float2half(acc[mi][ni][3] + bb.y));
            *reinterpret_cast<float2*>(out + (size_t)row0 * N_DIM + col) =
                make_float2(r00, r01);
            *reinterpret_cast<float2*>(out + (size_t)(row0 + 8) * N_DIM + col) =
                make_float2(r10, r11);
        }
    }
}

// ---------------------------------------------------------------------------
// Inputs (metadata order): x fp32, qweight int32, qzeros int32, scales fp32,
// bias fp32. Output fp32 (harness transports fp16 tensors as float32).
// ---------------------------------------------------------------------------
extern "C" void kernel_launch(void* const* d_in, const int* in_sizes, int n_in,
                              void* d_out, int out_size)
{
    const float* x    = (const float*)d_in[0];
    const int*   qw   = (const int*)d_in[1];
    const int*   qz   = (const int*)d_in[2];
    const float* sc   = (const float*)d_in[3];
    const float* bias = (const float*)d_in[4];
    float*       out  = (float*)d_out;

    const size_t xtotal = (size_t)M_DIM * K_DIM;
    convert_x_kernel<<<(unsigned)((xtotal / 8 + 255) / 256), 256>>>(x);

    const int total = K_DIM * NPACK;
    dequant_kernel<<<(total + 255) / 256, 256>>>(qw, qz, sc);

    const int smem_bytes =
        (NSTAGE * SA_STAGE_HALVES + NSTAGE * SB_STAGE_HALVES) * (int)sizeof(__half);
    cudaFuncSetAttribute(gemm_kernel,
                         cudaFuncAttributeMaxDynamicSharedMemorySize, smem_bytes);
    dim3 grid(M_DIM / BM, N_DIM / BN);   // (64, 86)
    gemm_kernel<<<grid, NT, smem_bytes>>>(bias, out);
}

// round 16
// speedup vs baseline: 1.0167x; 1.0167x over previous
#include <cuda_runtime.h>
#include <cuda_fp16.h>
#include <cstdint>

// Problem constants (fixed shapes)
#define K_DIM 4096
#define N_DIM 11008
#define M_DIM 8192
#define NPACK 1376   /* N/8 packed int32 columns */

// GEMM tiling: CTA 128x128x64, 8 warps (2x4), warp tile 64x32, 3-stage cp.async
// (exact R6 geometry) + ks PHASE STAGGERING across wn-warp-groups to overlap
// crossbar (LDSM) and tensor (HMMA) pipe usage across the SM.
#define BM 128
#define BN 128
#define BK 64
#define NSTAGE 3
#define SA_STRIDE 72    /* halves per A row (144B), conflict-free ldmatrix */
#define SB_STRIDE 136   /* halves per B row (272B), conflict-free ldmatrix */
#define SA_STAGE_HALVES (BM * SA_STRIDE)   /* 9216  -> 18432 B */
#define SB_STAGE_HALVES (BK * SB_STRIDE)   /* 8704  -> 17408 B */
#define KT_ITERS (K_DIM / BK)              /* 64 */

// Scratch (static __device__ arrays: allowed)
__device__ __half g_W[(size_t)K_DIM * N_DIM];   // 90 MB dequantized weights (fp16, [K,N])
__device__ __half g_X[(size_t)M_DIM * K_DIM];   // 64 MB activations fp32->fp16

#define CP_ASYNC_CG(dst, src) \
    asm volatile("cp.async.cg.shared.global [%0], [%1], 16;\n" :: "r"(dst), "l"(src))
#define CP_COMMIT() asm volatile("cp.async.commit_group;\n" ::)
#define CP_WAIT(n)  asm volatile("cp.async.wait_group %0;\n" :: "n"(n))

// ---------------------------------------------------------------------------
// Kernel 0: convert x (fp32 from harness) -> fp16 g_X. 8 elements/thread.
// ---------------------------------------------------------------------------
__global__ void convert_x_kernel(const float* __restrict__ x)
{
    size_t i = ((size_t)blockIdx.x * blockDim.x + threadIdx.x) * 8;
    if (i >= (size_t)M_DIM * K_DIM) return;
    float4 f0 = *reinterpret_cast<const float4*>(x + i);
    float4 f1 = *reinterpret_cast<const float4*>(x + i + 4);
    __half h[8];
    h[0] = __float2half(f0.x); h[1] = __float2half(f0.y);
    h[2] = __float2half(f0.z); h[3] = __float2half(f0.w);
    h[4] = __float2half(f1.x); h[5] = __float2half(f1.y);
    h[6] = __float2half(f1.z); h[7] = __float2half(f1.w);
    *reinterpret_cast<uint4*>(&g_X[i]) = *reinterpret_cast<uint4*>(h);
}

// ---------------------------------------------------------------------------
// Kernel 1: AWQ 4-bit dequant -> fp16 g_W[k][n] (nibble order {0,4,1,5,2,6,3,7})
// ---------------------------------------------------------------------------
__global__ void dequant_kernel(const int* __restrict__ qw,
                               const int* __restrict__ qz,
                               const float* __restrict__ sc)
{
    int idx = blockIdx.x * blockDim.x + threadIdx.x;
    if (idx >= K_DIM * NPACK) return;
    int k = idx / NPACK;
    int p = idx - k * NPACK;

    int w = qw[idx];
    int z = qz[(k >> 7) * NPACK + p];

    const float* sp = sc + (size_t)(k >> 7) * N_DIM + p * 8;
    float4 s0 = *reinterpret_cast<const float4*>(sp);
    float4 s1 = *reinterpret_cast<const float4*>(sp + 4);
    float sf[8] = {s0.x, s0.y, s0.z, s0.w, s1.x, s1.y, s1.z, s1.w};

    const int shift[8] = {0, 16, 4, 20, 8, 24, 12, 28};
    __half outv[8];
#pragma unroll
    for (int j = 0; j < 8; j++) {
        int iw = (w >> shift[j]) & 15;
        int iz = (z >> shift[j]) & 15;
        outv[j] = __float2half((float)(iw - iz) * sf[j]);
    }
    *reinterpret_cast<uint4*>(&g_W[(size_t)k * N_DIM + p * 8]) =
        *reinterpret_cast<uint4*>(outv);
}

// ---------------------------------------------------------------------------
// Kernel 2: fp16 mma.sync GEMM, fp32 accum, fused bias, fp32 output.
// 128x128x64 CTA tile, warp tile 64x32, 3-stage cp.async pipeline,
// one __syncthreads per K-chunk, ks phase staggered per wn-warp-group.
// ---------------------------------------------------------------------------
__global__ void __launch_bounds__(256, 2)
gemm_kernel(const float* __restrict__ bias, float* __restrict__ out)
{
    extern __shared__ __half dsm[];
    __half* sA = dsm;                                    // [NSTAGE][BM][SA_STRIDE]
    __half* sB = dsm + NSTAGE * SA_STAGE_HALVES;         // [NSTAGE][BK][SB_STRIDE]

    const int tid  = threadIdx.x;
    const int wid  = tid >> 5;
    const int lane = tid & 31;
    const int bm0  = blockIdx.x * BM;
    const int bn0  = blockIdx.y * BN;

    const int wm = (wid >> 2) * 64;   // warp row offset
    const int wn = (wid & 3) * 32;    // warp col offset
    const int kphase = wid & 3;       // per-warp-group ks rotation

    float acc[4][4][4];
#pragma unroll
    for (int i = 0; i < 4; i++)
#pragma unroll
        for (int j = 0; j < 4; j++)
#pragma unroll
            for (int r = 0; r < 4; r++) acc[i][j][r] = 0.f;

    const __half* gA = g_X + (size_t)bm0 * K_DIM;
    const __half* gB = g_W + bn0;

    // Loader: A = 1024 16B-chunks (row=c>>3, k8=c&7); B = 1024 (row=d>>4, n8=d&15)
#define ISSUE_STAGE(buf, kt_)                                                        \
    do {                                                                             \
        const int kk = (kt_) * BK;                                                   \
        __half* aS = sA + (buf) * SA_STAGE_HALVES;                                   \
        __half* bS = sB + (buf) * SB_STAGE_HALVES;                                   \
        _Pragma("unroll")                                                            \
        for (int i = 0; i < 4; i++) {                                                \
            int c = tid + i * 256;                                                   \
            int row = c >> 3, k8 = c & 7;                                            \
            uint32_t dst = (uint32_t)__cvta_generic_to_shared(                       \
                aS + row * SA_STRIDE + k8 * 8);                                      \
            CP_ASYNC_CG(dst, gA + (size_t)row * K_DIM + kk + k8 * 8);                \
        }                                                                            \
        _Pragma("unroll")                                                            \
        for (int i = 0; i < 4; i++) {                                                \
            int d = tid + i * 256;                                                   \
            int row = d >> 4, n8 = d & 15;                                           \
            uint32_t dst = (uint32_t)__cvta_generic_to_shared(                       \
                bS + row * SB_STRIDE + n8 * 8);                                      \
            CP_ASYNC_CG(dst, gB + (size_t)(kk + row) * N_DIM + n8 * 8);              \
        }                                                                            \
        CP_COMMIT();                                                                 \
    } while (0)

    // Prologue: prefetch stages 0,1
    ISSUE_STAGE(0, 0);
    ISSUE_STAGE(1, 1);

    for (int kt = 0; kt < KT_ITERS; kt++) {
        const int s = kt % 3;
        if (kt + 2 < KT_ITERS) CP_WAIT(1);
        else                   CP_WAIT(0);
        __syncthreads();   // stage kt visible; all warps done with buffer being refilled
        if (kt + 2 < KT_ITERS) ISSUE_STAGE((kt + 2) % 3, kt + 2);

        const __half* aS = sA + s * SA_STAGE_HALVES;
        const __half* bS = sB + s * SB_STAGE_HALVES;

#pragma unroll
        for (int ks = 0; ks < 4; ks++) {
            // Phase-staggered ks: each wn-warp-group starts at a different k16
            // so LDSM (crossbar) and HMMA (tensor) interleave across the SM.
            const int k16 = ((ks + kphase) & 3) * 16;
            uint32_t a[4][4];
#pragma unroll
            for (int mi = 0; mi < 4; mi++) {
                uint32_t addr = (uint32_t)__cvta_generic_to_shared(
                    aS + (wm + mi * 16 + (lane & 15)) * SA_STRIDE + k16 + 8 * (lane >> 4));
                asm volatile(
                    "ldmatrix.sync.aligned.m8n8.x4.shared.b16 {%0,%1,%2,%3}, [%4];"
                    : "=r"(a[mi][0]), "=r"(a[mi][1]), "=r"(a[mi][2]), "=r"(a[mi][3])
                    : "r"(addr));
            }
            uint32_t b[4][2];
#pragma unroll
            for (int nj = 0; nj < 2; nj++) {
                uint32_t t0, t1, t2, t3;
                uint32_t addr = (uint32_t)__cvta_generic_to_shared(
                    bS + (k16 + (lane & 15)) * SB_STRIDE + wn + nj * 16 + 8 * (lane >> 4));
                asm volatile(
                    "ldmatrix.sync.aligned.m8n8.x4.trans.shared.b16 {%0,%1,%2,%3}, [%4];"
                    : "=r"(t0), "=r"(t1), "=r"(t2), "=r"(t3)
                    : "r"(addr));
                b[nj * 2 + 0][0] = t0; b[nj * 2 + 0][1] = t1;
                b[nj * 2 + 1][0] = t2; b[nj * 2 + 1][1] = t3;
            }
#pragma unroll
            for (int mi = 0; mi < 4; mi++)
#pragma unroll
                for (int ni = 0; ni < 4; ni++) {
                    asm volatile(
                        "mma.sync.aligned.m16n8k16.row.col.f32.f16.f16.f32 "
                        "{%0,%1,%2,%3}, {%4,%5,%6,%7}, {%8,%9}, {%0,%1,%2,%3};"
                        : "+f"(acc[mi][ni][0]), "+f"(acc[mi][ni][1]),
                          "+f"(acc[mi][ni][2]), "+f"(acc[mi][ni][3])
                        : "r"(a[mi][0]), "r"(a[mi][1]), "r"(a[mi][2]), "r"(a[mi][3]),
                          "r"(b[ni][0]), "r"(b[ni][1]));
                }
        }
    }

    // Epilogue: fp32 acc + fp32 bias -> fp16 round -> fp32 output, float2 stores
#pragma unroll
    for (int mi = 0; mi < 4; mi++) {
        int row0 = bm0 + wm + mi * 16 + (lane >> 2);
#pragma unroll
        for (int ni = 0; ni < 4; ni++) {
            int col = bn0 + wn + ni * 8 + (lane & 3) * 2;
            float2 bb = *reinterpret_cast<const float2*>(bias + col);
            float r00 = __half2float(__float2half(acc[mi][ni][0] + bb.x));
            float r01 = __half2float(__float2half(acc[mi][ni][1] + bb.y));
            float r10 = __half2float(__float2half(acc[mi][ni][2] + bb.x));
            float r11 = __half2float(__float2half(acc[mi][ni][3] + bb.y));
            *reinterpret_cast<float2*>(out + (size_t)row0 * N_DIM + col) =
                make_float2(r00, r01);
            *reinterpret_cast<float2*>(out + (size_t)(row0 + 8) * N_DIM + col) =
                make_float2(r10, r11);
        }
    }
}

// ---------------------------------------------------------------------------
// Inputs (metadata order): x fp32, qweight int32, qzeros int32, scales fp32,
// bias fp32. Output fp32 (harness transports fp16 tensors as float32).
// ---------------------------------------------------------------------------
extern "C" void kernel_launch(void* const* d_in, const int* in_sizes, int n_in,
                              void* d_out, int out_size)
{
    const float* x    = (const float*)d_in[0];
    const int*   qw   = (const int*)d_in[1];
    const int*   qz   = (const int*)d_in[2];
    const float* sc   = (const float*)d_in[3];
    const float* bias = (const float*)d_in[4];
    float*       out  = (float*)d_out;

    const size_t xtotal = (size_t)M_DIM * K_DIM;
    convert_x_kernel<<<(unsigned)((xtotal / 8 + 255) / 256), 256>>>(x);

    const int total = K_DIM * NPACK;
    dequant_kernel<<<(total + 255) / 256, 256>>>(qw, qz, sc);

    const int smem_bytes =
        (NSTAGE * SA_STAGE_HALVES + NSTAGE * SB_STAGE_HALVES) * (int)sizeof(__half);
    cudaFuncSetAttribute(gemm_kernel,
                         cudaFuncAttributeMaxDynamicSharedMemorySize, smem_bytes);
    dim3 grid(M_DIM / BM, N_DIM / BN);   // (64, 86)
    gemm_kernel<<<grid, 256, smem_bytes>>>(bias, out);
}

// round 17
// speedup vs baseline: 1.0470x; 1.0297x over previous
#include <cuda_runtime.h>
#include <cuda_fp16.h>
#include <cstdint>

// Problem constants (fixed shapes)
#define K_DIM 4096
#define N_DIM 11008
#define M_DIM 8192
#define NPACK 1376   /* N/8 packed int32 columns */

// GEMM tiling: CTA 128x128x64, 8 warps (2x4), warp tile 64x32, 3-stage cp.async
// (exact R6 geometry -- measured equilibrium of the mma.sync design space).
#define BM 128
#define BN 128
#define BK 64
#define NSTAGE 3
#define SA_STRIDE 72    /* halves per A row (144B), conflict-free ldmatrix */
#define SB_STRIDE 136   /* halves per B row (272B), conflict-free ldmatrix */
#define SA_STAGE_HALVES (BM * SA_STRIDE)   /* 9216  -> 18432 B */
#define SB_STAGE_HALVES (BK * SB_STRIDE)   /* 8704  -> 17408 B */
#define KT_ITERS (K_DIM / BK)              /* 64 */

// Aux kernel split: first NB_CONV blocks convert x, rest dequantize W.
#define NB_CONV 16384                      /* 16384*256*8 = 32M x elems */
#define NB_DEQ  22016                      /* 4096*1376/256 */

// Scratch (static __device__ arrays: allowed)
__device__ __half g_W[(size_t)K_DIM * N_DIM];   // 90 MB dequantized weights (fp16, [K,N])
__device__ __half g_X[(size_t)M_DIM * K_DIM];   // 64 MB activations fp32->fp16

#define CP_ASYNC_CG(dst, src) \
    asm volatile("cp.async.cg.shared.global [%0], [%1], 16;\n" :: "r"(dst), "l"(src))
#define CP_COMMIT() asm volatile("cp.async.commit_group;\n" ::)
#define CP_WAIT(n)  asm volatile("cp.async.wait_group %0;\n" :: "n"(n))

// ---------------------------------------------------------------------------
// Kernel 0: merged prep. Blocks [0,NB_CONV): x fp32->fp16. Blocks
// [NB_CONV, NB_CONV+NB_DEQ): AWQ dequant (nibble order {0,4,1,5,2,6,3,7}).
// ---------------------------------------------------------------------------
__global__ void prep_kernel(const float* __restrict__ x,
                            const int* __restrict__ qw,
                            const int* __restrict__ qz,
                            const float* __restrict__ sc)
{
    if (blockIdx.x < NB_CONV) {
        size_t i = ((size_t)blockIdx.x * blockDim.x + threadIdx.x) * 8;
        float4 f0 = *reinterpret_cast<const float4*>(x + i);
        float4 f1 = *reinterpret_cast<const float4*>(x + i + 4);
        __half h[8];
        h[0] = __float2half(f0.x); h[1] = __float2half(f0.y);
        h[2] = __float2half(f0.z); h[3] = __float2half(f0.w);
        h[4] = __float2half(f1.x); h[5] = __float2half(f1.y);
        h[6] = __float2half(f1.z); h[7] = __float2half(f1.w);
        *reinterpret_cast<uint4*>(&g_X[i]) = *reinterpret_cast<uint4*>(h);
    } else {
        int idx = (blockIdx.x - NB_CONV) * blockDim.x + threadIdx.x;
        int k = idx / NPACK;
        int p = idx - k * NPACK;

        int w = qw[idx];
        int z = qz[(k >> 7) * NPACK + p];

        const float* sp = sc + (size_t)(k >> 7) * N_DIM + p * 8;
        float4 s0 = *reinterpret_cast<const float4*>(sp);
        float4 s1 = *reinterpret_cast<const float4*>(sp + 4);
        float sf[8] = {s0.x, s0.y, s0.z, s0.w, s1.x, s1.y, s1.z, s1.w};

        const int shift[8] = {0, 16, 4, 20, 8, 24, 12, 28};
        __half outv[8];
#pragma unroll
        for (int j = 0; j < 8; j++) {
            int iw = (w >> shift[j]) & 15;
            int iz = (z >> shift[j]) & 15;
            outv[j] = __float2half((float)(iw - iz) * sf[j]);
        }
        *reinterpret_cast<uint4*>(&g_W[(size_t)k * N_DIM + p * 8]) =
            *reinterpret_cast<uint4*>(outv);
    }
}

// ---------------------------------------------------------------------------
// Kernel 1: fp16 mma.sync GEMM, fp32 accum, fused bias, fp32 output.
// 128x128x64 CTA tile, warp tile 64x32, 3-stage cp.async pipeline,
// one __syncthreads per K-chunk. Epilogue uses streaming stores (.cs)
// to keep the 360MB output stream from evicting W/A panels in L2.
// ---------------------------------------------------------------------------
__global__ void __launch_bounds__(256, 2)
gemm_kernel(const float* __restrict__ bias, float* __restrict__ out)
{
    extern __shared__ __half dsm[];
    __half* sA = dsm;                                    // [NSTAGE][BM][SA_STRIDE]
    __half* sB = dsm + NSTAGE * SA_STAGE_HALVES;         // [NSTAGE][BK][SB_STRIDE]

    const int tid  = threadIdx.x;
    const int wid  = tid >> 5;
    const int lane = tid & 31;
    const int bm0  = blockIdx.x * BM;
    const int bn0  = blockIdx.y * BN;

    const int wm = (wid >> 2) * 64;   // warp row offset
    const int wn = (wid & 3) * 32;    // warp col offset

    float acc[4][4][4];
#pragma unroll
    for (int i = 0; i < 4; i++)
#pragma unroll
        for (int j = 0; j < 4; j++)
#pragma unroll
            for (int r = 0; r < 4; r++) acc[i][j][r] = 0.f;

    const __half* gA = g_X + (size_t)bm0 * K_DIM;
    const __half* gB = g_W + bn0;

    // Loader: A = 1024 16B-chunks (row=c>>3, k8=c&7); B = 1024 (row=d>>4, n8=d&15)
#define ISSUE_STAGE(buf, kt_)                                                        \
    do {                                                                             \
        const int kk = (kt_) * BK;                                                   \
        __half* aS = sA + (buf) * SA_STAGE_HALVES;                                   \
        __half* bS = sB + (buf) * SB_STAGE_HALVES;                                   \
        _Pragma("unroll")                                                            \
        for (int i = 0; i < 4; i++) {                                                \
            int c = tid + i * 256;                                                   \
            int row = c >> 3, k8 = c & 7;                                            \
            uint32_t dst = (uint32_t)__cvta_generic_to_shared(                       \
                aS + row * SA_STRIDE + k8 * 8);                                      \
            CP_ASYNC_CG(dst, gA + (size_t)row * K_DIM + kk + k8 * 8);                \
        }                                                                            \
        _Pragma("unroll")                                                            \
        for (int i = 0; i < 4; i++) {                                                \
            int d = tid + i * 256;                                                   \
            int row = d >> 4, n8 = d & 15;                                           \
            uint32_t dst = (uint32_t)__cvta_generic_to_shared(                       \
                bS + row * SB_STRIDE + n8 * 8);                                      \
            CP_ASYNC_CG(dst, gB + (size_t)(kk + row) * N_DIM + n8 * 8);              \
        }                                                                            \
        CP_COMMIT();                                                                 \
    } while (0)

    // Prologue: prefetch stages 0,1
    ISSUE_STAGE(0, 0);
    ISSUE_STAGE(1, 1);

    for (int kt = 0; kt < KT_ITERS; kt++) {
        const int s = kt % 3;
        if (kt + 2 < KT_ITERS) CP_WAIT(1);
        else                   CP_WAIT(0);
        __syncthreads();   // stage kt visible; all warps done with buffer being refilled
        if (kt + 2 < KT_ITERS) ISSUE_STAGE((kt + 2) % 3, kt + 2);

        const __half* aS = sA + s * SA_STAGE_HALVES;
        const __half* bS = sB + s * SB_STAGE_HALVES;

#pragma unroll
        for (int ks = 0; ks < 4; ks++) {
            const int k16 = ks * 16;
            uint32_t a[4][4];
#pragma unroll
            for (int mi = 0; mi < 4; mi++) {
                uint32_t addr = (uint32_t)__cvta_generic_to_shared(
                    aS + (wm + mi * 16 + (lane & 15)) * SA_STRIDE + k16 + 8 * (lane >> 4));
                asm volatile(
                    "ldmatrix.sync.aligned.m8n8.x4.shared.b16 {%0,%1,%2,%3}, [%4];"
                    : "=r"(a[mi][0]), "=r"(a[mi][1]), "=r"(a[mi][2]), "=r"(a[mi][3])
                    : "r"(addr));
            }
            uint32_t b[4][2];
#pragma unroll
            for (int nj = 0; nj < 2; nj++) {
                uint32_t t0, t1, t2, t3;
                uint32_t addr = (uint32_t)__cvta_generic_to_shared(
                    bS + (k16 + (lane & 15)) * SB_STRIDE + wn + nj * 16 + 8 * (lane >> 4));
                asm volatile(
                    "ldmatrix.sync.aligned.m8n8.x4.trans.shared.b16 {%0,%1,%2,%3}, [%4];"
                    : "=r"(t0), "=r"(t1), "=r"(t2), "=r"(t3)
                    : "r"(addr));
                b[nj * 2 + 0][0] = t0; b[nj * 2 + 0][1] = t1;
                b[nj * 2 + 1][0] = t2; b[nj * 2 + 1][1] = t3;
            }
#pragma unroll
            for (int mi = 0; mi < 4; mi++)
#pragma unroll
                for (int ni = 0; ni < 4; ni++) {
                    asm volatile(
                        "mma.sync.aligned.m16n8k16.row.col.f32.f16.f16.f32 "
                        "{%0,%1,%2,%3}, {%4,%5,%6,%7}, {%8,%9}, {%0,%1,%2,%3};"
                        : "+f"(acc[mi][ni][0]), "+f"(acc[mi][ni][1]),
                          "+f"(acc[mi][ni][2]), "+f"(acc[mi][ni][3])
                        : "r"(a[mi][0]), "r"(a[mi][1]), "r"(a[mi][2]), "r"(a[mi][3]),
                          "r"(b[ni][0]), "r"(b[ni][1]));
                }
        }
    }

    // Epilogue: fp32 acc + fp32 bias -> fp16 round -> fp32 output.
    // Streaming stores: output is write-once, keep it out of L2's working set.
#pragma unroll
    for (int mi = 0; mi < 4; mi++) {
        int row0 = bm0 + wm + mi * 16 + (lane >> 2);
#pragma unroll
        for (int ni = 0; ni < 4; ni++) {
            int col = bn0 + wn + ni * 8 + (lane & 3) * 2;
            float2 bb = *reinterpret_cast<const float2*>(bias + col);
            float r00 = __half2float(__float2half(acc[mi][ni][0] + bb.x));
            float r01 = __half2float(__float2half(acc[mi][ni][1] + bb.y));
            float r10 = __half2float(__float2half(acc[mi][ni][2] + bb.x));
            float r11 = __half2float(__float2half(acc[mi][ni][3] + bb.y));
            float* p0 = out + (size_t)row0 * N_DIM + col;
            float* p1 = out + (size_t)(row0 + 8) * N_DIM + col;
            asm volatile("st.global.cs.v2.f32 [%0], {%1,%2};"
                         :: "l"(p0), "f"(r00), "f"(r01) : "memory");
            asm volatile("st.global.cs.v2.f32 [%0], {%1,%2};"
                         :: "l"(p1), "f"(r10), "f"(r11) : "memory");
        }
    }
}

// ---------------------------------------------------------------------------
// Inputs (metadata order): x fp32, qweight int32, qzeros int32, scales fp32,
// bias fp32. Output fp32 (harness transports fp16 tensors as float32).
// ---------------------------------------------------------------------------
extern "C" void kernel_launch(void* const* d_in, const int* in_sizes, int n_in,
                              void* d_out, int out_size)
{
    const float* x    = (const float*)d_in[0];
    const int*   qw   = (const int*)d_in[1];
    const int*   qz   = (const int*)d_in[2];
    const float* sc   = (const float*)d_in[3];
    const float* bias = (const float*)d_in[4];
    float*       out  = (float*)d_out;

    prep_kernel<<<NB_CONV + NB_DEQ, 256>>>(x, qw, qz, sc);

    const int smem_bytes =
        (NSTAGE * SA_STAGE_HALVES + NSTAGE * SB_STAGE_HALVES) * (int)sizeof(__half);
    cudaFuncSetAttribute(gemm_kernel,
                         cudaFuncAttributeMaxDynamicSharedMemorySize, smem_bytes);
    dim3 grid(M_DIM / BM, N_DIM / BN);   // (64, 86)
    gemm_kernel<<<grid, 256, smem_bytes>>>(bias, out);
}